// round 10
// baseline (speedup 1.0000x reference)
#include <cuda_runtime.h>
#include <math.h>

#define N_NODES 50000
#define N_EDGES 1600000
#define DIM     128
#define NHEADS  4
#define NEG_SLOPE 0.2f
#define CAP     128   // smem fast-path neighbor cap (Poisson(32) max deg ~70)

// ---------------- scratch (static device arrays; no allocation) ----------------
__device__ int   g_deg   [N_NODES];
__device__ int   g_rowptr[N_NODES + 1];
__device__ int   g_cursor[N_NODES];
__device__ int   g_cols  [N_EDGES];
__device__ float g_hq    [N_NODES * NHEADS];
__device__ float g_kact  [N_NODES * NHEADS];
__device__ float g_qagg  [N_NODES * NHEADS];
__device__ float g_hproj [(size_t)N_NODES * DIM];

// ---------------- helpers ----------------
static __device__ __forceinline__ float leaky_f(float v) {
    return v >= 0.f ? v : NEG_SLOPE * v;
}
static __device__ __forceinline__ unsigned long long pack2(float lo, float hi) {
    unsigned long long r;
    asm("mov.b64 %0, {%1,%2};" : "=l"(r) : "f"(lo), "f"(hi));
    return r;
}
static __device__ __forceinline__ void unpack2(unsigned long long v, float& lo, float& hi) {
    asm("mov.b64 {%0,%1}, %2;" : "=f"(lo), "=f"(hi) : "l"(v));
}

// ---------------- CSR build ----------------

__global__ void k_zero_deg() {
    int i = blockIdx.x * blockDim.x + threadIdx.x;
    if (i < N_NODES) g_deg[i] = 0;
}

// 4 edges per thread: one int4 load, 4 independent REDs (latency overlap)
__global__ void k_hist(const int* __restrict__ ei) {
    int t = blockIdx.x * blockDim.x + threadIdx.x;
    int base = t * 4;
    if (base >= N_EDGES) return;
    int4 r = *(const int4*)&ei[base];   // N_EDGES % 4 == 0 -> aligned, in-bounds
    atomicAdd(&g_deg[r.x], 1);
    atomicAdd(&g_deg[r.y], 1);
    atomicAdd(&g_deg[r.z], 1);
    atomicAdd(&g_deg[r.w], 1);
}

__global__ __launch_bounds__(1024) void k_scan() {
    __shared__ int sh[1024];
    const int T = 1024;
    const int per = (N_NODES + T - 1) / T;
    int t = threadIdx.x;
    int base = t * per;
    int s = 0;
    for (int i = 0; i < per; i++) {
        int idx = base + i;
        if (idx < N_NODES) s += g_deg[idx];
    }
    sh[t] = s;
    __syncthreads();
    for (int off = 1; off < T; off <<= 1) {
        int v = (t >= off) ? sh[t - off] : 0;
        __syncthreads();
        sh[t] += v;
        __syncthreads();
    }
    int run = (t == 0) ? 0 : sh[t - 1];
    for (int i = 0; i < per; i++) {
        int idx = base + i;
        if (idx < N_NODES) {
            g_rowptr[idx] = run;
            g_cursor[idx] = run;
            run += g_deg[idx];
        }
    }
    if (t == T - 1) g_rowptr[N_NODES] = run;
}

// 4 edges per thread: two int4 loads, 4 independent atomic+store chains
__global__ void k_scatter(const int* __restrict__ ei) {
    int t = blockIdx.x * blockDim.x + threadIdx.x;
    int base = t * 4;
    if (base >= N_EDGES) return;
    int4 r = *(const int4*)&ei[base];
    int4 c = *(const int4*)&ei[N_EDGES + base];
    int p0 = atomicAdd(&g_cursor[r.x], 1);
    int p1 = atomicAdd(&g_cursor[r.y], 1);
    int p2 = atomicAdd(&g_cursor[r.z], 1);
    int p3 = atomicAdd(&g_cursor[r.w], 1);
    g_cols[p0] = c.x;
    g_cols[p1] = c.y;
    g_cols[p2] = c.z;
    g_cols[p3] = c.w;
}

// ---------------- projections ----------------

__global__ void k_qk(const float* __restrict__ x,
                     const float* __restrict__ Wq,
                     const float* __restrict__ Wk) {
    int warp = (blockIdx.x * blockDim.x + threadIdx.x) >> 5;
    if (warp >= N_NODES) return;
    int lane = threadIdx.x & 31;

    float4 xv = *(const float4*)&x[(size_t)warp * DIM + lane * 4];
    float q[NHEADS], k[NHEADS];
#pragma unroll
    for (int h = 0; h < NHEADS; h++) {
        float4 wq = *(const float4*)&Wq[h * DIM + lane * 4];
        float4 wk = *(const float4*)&Wk[h * DIM + lane * 4];
        q[h] = xv.x * wq.x + xv.y * wq.y + xv.z * wq.z + xv.w * wq.w;
        k[h] = xv.x * wk.x + xv.y * wk.y + xv.z * wk.z + xv.w * wk.w;
    }
#pragma unroll
    for (int off = 16; off > 0; off >>= 1) {
#pragma unroll
        for (int h = 0; h < NHEADS; h++) {
            q[h] += __shfl_xor_sync(0xffffffffu, q[h], off);
            k[h] += __shfl_xor_sync(0xffffffffu, k[h], off);
        }
    }
    if (lane == 0) {
#pragma unroll
        for (int h = 0; h < NHEADS; h++) {
            g_hq[warp * NHEADS + h]   = q[h];
            g_kact[warp * NHEADS + h] = leaky_f(k[h]);
        }
    }
}

__global__ __launch_bounds__(256) void k_gemm(const float* __restrict__ x,
                                              const float* __restrict__ Wl,
                                              const float* __restrict__ bl) {
    __shared__ float xs[32][DIM];
    __shared__ float ws[32][DIM];

    const int tid = threadIdx.x;
    const int tm = tid >> 4;
    const int tn = tid & 15;
    const int m0 = blockIdx.x * 128;

    unsigned long long acc[8][4];
#pragma unroll
    for (int i = 0; i < 8; i++)
#pragma unroll
        for (int j = 0; j < 4; j++) acc[i][j] = 0ull;

    const int lrow = tid >> 1;
    const int lk   = (tid & 1) * 16;

    for (int k0 = 0; k0 < DIM; k0 += 32) {
        __syncthreads();
        {
            int gm = m0 + lrow;
#pragma unroll
            for (int q = 0; q < 16; q += 4) {
                float4 v = make_float4(0.f, 0.f, 0.f, 0.f);
                if (gm < N_NODES)
                    v = *(const float4*)&x[(size_t)gm * DIM + k0 + lk + q];
                xs[lk + q + 0][lrow] = v.x;
                xs[lk + q + 1][lrow] = v.y;
                xs[lk + q + 2][lrow] = v.z;
                xs[lk + q + 3][lrow] = v.w;
            }
        }
        {
#pragma unroll
            for (int q = 0; q < 16; q += 4) {
                float4 w = *(const float4*)&Wl[(size_t)lrow * DIM + k0 + lk + q];
                ws[lk + q + 0][lrow] = w.x;
                ws[lk + q + 1][lrow] = w.y;
                ws[lk + q + 2][lrow] = w.z;
                ws[lk + q + 3][lrow] = w.w;
            }
        }
        __syncthreads();

#pragma unroll 8
        for (int kk = 0; kk < 32; kk++) {
            float4 a0 = *(const float4*)&xs[kk][tm * 8];
            float4 a1 = *(const float4*)&xs[kk][tm * 8 + 4];
            unsigned long long a2[8];
            a2[0] = pack2(a0.x, a0.x); a2[1] = pack2(a0.y, a0.y);
            a2[2] = pack2(a0.z, a0.z); a2[3] = pack2(a0.w, a0.w);
            a2[4] = pack2(a1.x, a1.x); a2[5] = pack2(a1.y, a1.y);
            a2[6] = pack2(a1.z, a1.z); a2[7] = pack2(a1.w, a1.w);
            unsigned long long b2[4];
#pragma unroll
            for (int j = 0; j < 4; j++) {
                float2 b = *(const float2*)&ws[kk][tn * 2 + 32 * j];
                b2[j] = pack2(b.x, b.y);
            }
#pragma unroll
            for (int i = 0; i < 8; i++)
#pragma unroll
                for (int j = 0; j < 4; j++)
                    asm volatile("fma.rn.f32x2 %0, %1, %2, %0;"
                                 : "+l"(acc[i][j]) : "l"(a2[i]), "l"(b2[j]));
        }
    }

#pragma unroll
    for (int j = 0; j < 4; j++) {
        int o = tn * 2 + 32 * j;
        float2 blv = *(const float2*)&bl[o];
#pragma unroll
        for (int i = 0; i < 8; i++) {
            int m = m0 + tm * 8 + i;
            if (m < N_NODES) {
                float lo, hi;
                unpack2(acc[i][j], lo, hi);
                *(float2*)&g_hproj[(size_t)m * DIM + o] =
                    make_float2(lo + blv.x, hi + blv.y);
            }
        }
    }
}

// ---------------- q_agg (warp per node, x2 unrolled gather) ----------------
__global__ void k_qagg_csr() {
    int node = (blockIdx.x * blockDim.x + threadIdx.x) >> 5;
    if (node >= N_NODES) return;
    int lane = threadIdx.x & 31;
    int rp0 = g_rowptr[node], rp1 = g_rowptr[node + 1];
    float4 acc = make_float4(0.f, 0.f, 0.f, 0.f);
    int j = rp0 + lane;
    for (; j + 32 < rp1; j += 64) {
        int c0 = g_cols[j];
        int c1 = g_cols[j + 32];
        float4 h0 = ((const float4*)g_hq)[c0];
        float4 h1 = ((const float4*)g_hq)[c1];
        acc.x += h0.x + h1.x; acc.y += h0.y + h1.y;
        acc.z += h0.z + h1.z; acc.w += h0.w + h1.w;
    }
    for (; j < rp1; j += 32) {
        int c = g_cols[j];
        float4 h = ((const float4*)g_hq)[c];
        acc.x += h.x; acc.y += h.y; acc.z += h.z; acc.w += h.w;
    }
#pragma unroll
    for (int off = 16; off > 0; off >>= 1) {
        acc.x += __shfl_xor_sync(0xffffffffu, acc.x, off);
        acc.y += __shfl_xor_sync(0xffffffffu, acc.y, off);
        acc.z += __shfl_xor_sync(0xffffffffu, acc.z, off);
        acc.w += __shfl_xor_sync(0xffffffffu, acc.w, off);
    }
    if (lane == 0) ((float4*)g_qagg)[node] = acc;
}

// ---------------- fused softmax + aggregation (warp per node) ----------------
__global__ __launch_bounds__(256) void k_fused(float* __restrict__ out) {
    __shared__ float4 sex[8][CAP];   // per-warp per-edge exp values (4 heads)
    __shared__ float  sal[8][CAP];   // per-warp per-edge alpha_mean

    const int w    = threadIdx.x >> 5;
    const int lane = threadIdx.x & 31;
    const int node = (blockIdx.x * blockDim.x + threadIdx.x) >> 5;
    if (node >= N_NODES) return;

    const int rp0 = g_rowptr[node], rp1 = g_rowptr[node + 1];
    const int deg = rp1 - rp0;

    float4 acc = make_float4(0.f, 0.f, 0.f, 0.f);

    if (deg > 0 && deg <= CAP) {
        const float4 kact = ((const float4*)g_kact)[node];

        // pass 1: scores -> smem, running max
        float4 m = make_float4(-INFINITY, -INFINITY, -INFINITY, -INFINITY);
        for (int jj = lane; jj < deg; jj += 32) {
            int c = __ldg(&g_cols[rp0 + jj]);
            float4 q = ((const float4*)g_qagg)[c];
            float4 s = make_float4(kact.x * q.x, kact.y * q.y,
                                   kact.z * q.z, kact.w * q.w);
            sex[w][jj] = s;
            m.x = fmaxf(m.x, s.x); m.y = fmaxf(m.y, s.y);
            m.z = fmaxf(m.z, s.z); m.w = fmaxf(m.w, s.w);
        }
#pragma unroll
        for (int off = 16; off > 0; off >>= 1) {
            m.x = fmaxf(m.x, __shfl_xor_sync(0xffffffffu, m.x, off));
            m.y = fmaxf(m.y, __shfl_xor_sync(0xffffffffu, m.y, off));
            m.z = fmaxf(m.z, __shfl_xor_sync(0xffffffffu, m.z, off));
            m.w = fmaxf(m.w, __shfl_xor_sync(0xffffffffu, m.w, off));
        }

        // pass 2: exp in smem, running sum
        float4 sum = make_float4(0.f, 0.f, 0.f, 0.f);
        for (int jj = lane; jj < deg; jj += 32) {
            float4 s = sex[w][jj];
            float4 ex = make_float4(__expf(s.x - m.x), __expf(s.y - m.y),
                                    __expf(s.z - m.z), __expf(s.w - m.w));
            sex[w][jj] = ex;
            sum.x += ex.x; sum.y += ex.y; sum.z += ex.z; sum.w += ex.w;
        }
#pragma unroll
        for (int off = 16; off > 0; off >>= 1) {
            sum.x += __shfl_xor_sync(0xffffffffu, sum.x, off);
            sum.y += __shfl_xor_sync(0xffffffffu, sum.y, off);
            sum.z += __shfl_xor_sync(0xffffffffu, sum.z, off);
            sum.w += __shfl_xor_sync(0xffffffffu, sum.w, off);
        }
        float4 inv = make_float4(0.25f / (sum.x + 1e-8f), 0.25f / (sum.y + 1e-8f),
                                 0.25f / (sum.z + 1e-8f), 0.25f / (sum.w + 1e-8f));

        // pass 2.5: alpha_mean -> smem
        for (int jj = lane; jj < deg; jj += 32) {
            float4 ex = sex[w][jj];
            sal[w][jj] = ex.x * inv.x + ex.y * inv.y + ex.z * inv.z + ex.w * inv.w;
        }
        __syncwarp();

        // pass 3: aggregate h_proj, unrolled x8 for MLP
        int jj = 0;
        for (; jj + 8 <= deg; jj += 8) {
            float a[8]; int c[8];
#pragma unroll
            for (int u = 0; u < 8; u++) {
                a[u] = sal[w][jj + u];
                c[u] = __ldg(&g_cols[rp0 + jj + u]);
            }
            float4 v[8];
#pragma unroll
            for (int u = 0; u < 8; u++)
                v[u] = *(const float4*)&g_hproj[(size_t)c[u] * DIM + lane * 4];
#pragma unroll
            for (int u = 0; u < 8; u++) {
                acc.x += a[u] * v[u].x; acc.y += a[u] * v[u].y;
                acc.z += a[u] * v[u].z; acc.w += a[u] * v[u].w;
            }
        }
        for (; jj < deg; jj++) {
            float a = sal[w][jj];
            int   c = __ldg(&g_cols[rp0 + jj]);
            float4 v = *(const float4*)&g_hproj[(size_t)c * DIM + lane * 4];
            acc.x += a * v.x; acc.y += a * v.y; acc.z += a * v.z; acc.w += a * v.w;
        }
    } else if (deg > CAP) {
        // fallback (correct for any degree; effectively never taken for this graph)
        const float4 kact = ((const float4*)g_kact)[node];
        float4 m = make_float4(-INFINITY, -INFINITY, -INFINITY, -INFINITY);
        for (int j = rp0 + lane; j < rp1; j += 32) {
            int c = g_cols[j];
            float4 q = ((const float4*)g_qagg)[c];
            m.x = fmaxf(m.x, kact.x * q.x); m.y = fmaxf(m.y, kact.y * q.y);
            m.z = fmaxf(m.z, kact.z * q.z); m.w = fmaxf(m.w, kact.w * q.w);
        }
#pragma unroll
        for (int off = 16; off > 0; off >>= 1) {
            m.x = fmaxf(m.x, __shfl_xor_sync(0xffffffffu, m.x, off));
            m.y = fmaxf(m.y, __shfl_xor_sync(0xffffffffu, m.y, off));
            m.z = fmaxf(m.z, __shfl_xor_sync(0xffffffffu, m.z, off));
            m.w = fmaxf(m.w, __shfl_xor_sync(0xffffffffu, m.w, off));
        }
        float4 sum = make_float4(0.f, 0.f, 0.f, 0.f);
        for (int j = rp0 + lane; j < rp1; j += 32) {
            int c = g_cols[j];
            float4 q = ((const float4*)g_qagg)[c];
            sum.x += __expf(kact.x * q.x - m.x);
            sum.y += __expf(kact.y * q.y - m.y);
            sum.z += __expf(kact.z * q.z - m.z);
            sum.w += __expf(kact.w * q.w - m.w);
        }
#pragma unroll
        for (int off = 16; off > 0; off >>= 1) {
            sum.x += __shfl_xor_sync(0xffffffffu, sum.x, off);
            sum.y += __shfl_xor_sync(0xffffffffu, sum.y, off);
            sum.z += __shfl_xor_sync(0xffffffffu, sum.z, off);
            sum.w += __shfl_xor_sync(0xffffffffu, sum.w, off);
        }
        float4 inv = make_float4(0.25f / (sum.x + 1e-8f), 0.25f / (sum.y + 1e-8f),
                                 0.25f / (sum.z + 1e-8f), 0.25f / (sum.w + 1e-8f));
        for (int jj = 0; jj < deg; jj++) {
            int c = __ldg(&g_cols[rp0 + jj]);
            float4 q = ((const float4*)g_qagg)[c];
            float a = __expf(kact.x * q.x - m.x) * inv.x
                    + __expf(kact.y * q.y - m.y) * inv.y
                    + __expf(kact.z * q.z - m.z) * inv.z
                    + __expf(kact.w * q.w - m.w) * inv.w;
            float4 v = *(const float4*)&g_hproj[(size_t)c * DIM + lane * 4];
            acc.x += a * v.x; acc.y += a * v.y; acc.z += a * v.z; acc.w += a * v.w;
        }
    }

    acc.x = leaky_f(acc.x); acc.y = leaky_f(acc.y);
    acc.z = leaky_f(acc.z); acc.w = leaky_f(acc.w);
    *(float4*)&out[(size_t)node * DIM + lane * 4] = acc;
}

// ---------------- launch ----------------
extern "C" void kernel_launch(void* const* d_in, const int* in_sizes, int n_in,
                              void* d_out, int out_size) {
    const float* x  = (const float*)d_in[0];
    const int*   ei = (const int*)d_in[1];
    const float* Wq = (const float*)d_in[2];
    const float* Wk = (const float*)d_in[3];
    const float* Wl = (const float*)d_in[4];
    const float* bl = (const float*)d_in[5];
    float* out = (float*)d_out;

    const int TB = 256;
    const int E4_BLOCKS = (N_EDGES / 4 + TB - 1) / TB;          // 1563
    const int NODE_WARP_BLOCKS = (N_NODES * 32 + TB - 1) / TB;  // 6250

    k_zero_deg<<<(N_NODES + TB - 1) / TB, TB>>>();
    k_hist<<<E4_BLOCKS, TB>>>(ei);
    k_scan<<<1, 1024>>>();
    k_scatter<<<E4_BLOCKS, TB>>>(ei);
    k_qk<<<NODE_WARP_BLOCKS, TB>>>(x, Wq, Wk);
    k_gemm<<<(N_NODES + 127) / 128, TB>>>(x, Wl, bl);
    k_qagg_csr<<<NODE_WARP_BLOCKS, TB>>>();
    k_fused<<<NODE_WARP_BLOCKS, TB>>>(out);
}

// round 11
// speedup vs baseline: 1.0350x; 1.0350x over previous
#include <cuda_runtime.h>
#include <cuda_fp16.h>
#include <math.h>

#define N_NODES 50000
#define N_EDGES 1600000
#define DIM     128
#define NHEADS  4
#define NEG_SLOPE 0.2f
#define CAP     128   // smem fast-path neighbor cap (Poisson(32) max deg ~70)

// ---------------- scratch (static device arrays; no allocation) ----------------
__device__ int    g_deg   [N_NODES];
__device__ int    g_rowptr[N_NODES + 1];
__device__ int    g_cursor[N_NODES];
__device__ int    g_cols  [N_EDGES];
__device__ float  g_hq    [N_NODES * NHEADS];
__device__ float  g_kact  [N_NODES * NHEADS];
__device__ float  g_qagg  [N_NODES * NHEADS];
__device__ __half g_hproj [(size_t)N_NODES * DIM];   // fp16 value matrix (halves gather bytes)

// ---------------- helpers ----------------
static __device__ __forceinline__ float leaky_f(float v) {
    return v >= 0.f ? v : NEG_SLOPE * v;
}
static __device__ __forceinline__ unsigned long long pack2(float lo, float hi) {
    unsigned long long r;
    asm("mov.b64 %0, {%1,%2};" : "=l"(r) : "f"(lo), "f"(hi));
    return r;
}
static __device__ __forceinline__ void unpack2(unsigned long long v, float& lo, float& hi) {
    asm("mov.b64 {%0,%1}, %2;" : "=f"(lo), "=f"(hi) : "l"(v));
}

// ---------------- CSR build ----------------

__global__ void k_zero_deg() {
    int i = blockIdx.x * blockDim.x + threadIdx.x;
    if (i < N_NODES) g_deg[i] = 0;
}

__global__ void k_hist(const int* __restrict__ ei) {
    int t = blockIdx.x * blockDim.x + threadIdx.x;
    int base = t * 4;
    if (base >= N_EDGES) return;
    int4 r = *(const int4*)&ei[base];
    atomicAdd(&g_deg[r.x], 1);
    atomicAdd(&g_deg[r.y], 1);
    atomicAdd(&g_deg[r.z], 1);
    atomicAdd(&g_deg[r.w], 1);
}

__global__ __launch_bounds__(1024) void k_scan() {
    __shared__ int sh[1024];
    const int T = 1024;
    const int per = (N_NODES + T - 1) / T;
    int t = threadIdx.x;
    int base = t * per;
    int s = 0;
    for (int i = 0; i < per; i++) {
        int idx = base + i;
        if (idx < N_NODES) s += g_deg[idx];
    }
    sh[t] = s;
    __syncthreads();
    for (int off = 1; off < T; off <<= 1) {
        int v = (t >= off) ? sh[t - off] : 0;
        __syncthreads();
        sh[t] += v;
        __syncthreads();
    }
    int run = (t == 0) ? 0 : sh[t - 1];
    for (int i = 0; i < per; i++) {
        int idx = base + i;
        if (idx < N_NODES) {
            g_rowptr[idx] = run;
            g_cursor[idx] = run;
            run += g_deg[idx];
        }
    }
    if (t == T - 1) g_rowptr[N_NODES] = run;
}

__global__ void k_scatter(const int* __restrict__ ei) {
    int t = blockIdx.x * blockDim.x + threadIdx.x;
    int base = t * 4;
    if (base >= N_EDGES) return;
    int4 r = *(const int4*)&ei[base];
    int4 c = *(const int4*)&ei[N_EDGES + base];
    int p0 = atomicAdd(&g_cursor[r.x], 1);
    int p1 = atomicAdd(&g_cursor[r.y], 1);
    int p2 = atomicAdd(&g_cursor[r.z], 1);
    int p3 = atomicAdd(&g_cursor[r.w], 1);
    g_cols[p0] = c.x;
    g_cols[p1] = c.y;
    g_cols[p2] = c.z;
    g_cols[p3] = c.w;
}

// ---------------- projections ----------------

__global__ void k_qk(const float* __restrict__ x,
                     const float* __restrict__ Wq,
                     const float* __restrict__ Wk) {
    int warp = (blockIdx.x * blockDim.x + threadIdx.x) >> 5;
    if (warp >= N_NODES) return;
    int lane = threadIdx.x & 31;

    float4 xv = *(const float4*)&x[(size_t)warp * DIM + lane * 4];
    float q[NHEADS], k[NHEADS];
#pragma unroll
    for (int h = 0; h < NHEADS; h++) {
        float4 wq = *(const float4*)&Wq[h * DIM + lane * 4];
        float4 wk = *(const float4*)&Wk[h * DIM + lane * 4];
        q[h] = xv.x * wq.x + xv.y * wq.y + xv.z * wq.z + xv.w * wq.w;
        k[h] = xv.x * wk.x + xv.y * wk.y + xv.z * wk.z + xv.w * wk.w;
    }
#pragma unroll
    for (int off = 16; off > 0; off >>= 1) {
#pragma unroll
        for (int h = 0; h < NHEADS; h++) {
            q[h] += __shfl_xor_sync(0xffffffffu, q[h], off);
            k[h] += __shfl_xor_sync(0xffffffffu, k[h], off);
        }
    }
    if (lane == 0) {
#pragma unroll
        for (int h = 0; h < NHEADS; h++) {
            g_hq[warp * NHEADS + h]   = q[h];
            g_kact[warp * NHEADS + h] = leaky_f(k[h]);
        }
    }
}

__global__ __launch_bounds__(256) void k_gemm(const float* __restrict__ x,
                                              const float* __restrict__ Wl,
                                              const float* __restrict__ bl) {
    __shared__ float xs[32][DIM];
    __shared__ float ws[32][DIM];

    const int tid = threadIdx.x;
    const int tm = tid >> 4;
    const int tn = tid & 15;
    const int m0 = blockIdx.x * 128;

    unsigned long long acc[8][4];
#pragma unroll
    for (int i = 0; i < 8; i++)
#pragma unroll
        for (int j = 0; j < 4; j++) acc[i][j] = 0ull;

    const int lrow = tid >> 1;
    const int lk   = (tid & 1) * 16;

    for (int k0 = 0; k0 < DIM; k0 += 32) {
        __syncthreads();
        {
            int gm = m0 + lrow;
#pragma unroll
            for (int q = 0; q < 16; q += 4) {
                float4 v = make_float4(0.f, 0.f, 0.f, 0.f);
                if (gm < N_NODES)
                    v = *(const float4*)&x[(size_t)gm * DIM + k0 + lk + q];
                xs[lk + q + 0][lrow] = v.x;
                xs[lk + q + 1][lrow] = v.y;
                xs[lk + q + 2][lrow] = v.z;
                xs[lk + q + 3][lrow] = v.w;
            }
        }
        {
#pragma unroll
            for (int q = 0; q < 16; q += 4) {
                float4 w = *(const float4*)&Wl[(size_t)lrow * DIM + k0 + lk + q];
                ws[lk + q + 0][lrow] = w.x;
                ws[lk + q + 1][lrow] = w.y;
                ws[lk + q + 2][lrow] = w.z;
                ws[lk + q + 3][lrow] = w.w;
            }
        }
        __syncthreads();

#pragma unroll 8
        for (int kk = 0; kk < 32; kk++) {
            float4 a0 = *(const float4*)&xs[kk][tm * 8];
            float4 a1 = *(const float4*)&xs[kk][tm * 8 + 4];
            unsigned long long a2[8];
            a2[0] = pack2(a0.x, a0.x); a2[1] = pack2(a0.y, a0.y);
            a2[2] = pack2(a0.z, a0.z); a2[3] = pack2(a0.w, a0.w);
            a2[4] = pack2(a1.x, a1.x); a2[5] = pack2(a1.y, a1.y);
            a2[6] = pack2(a1.z, a1.z); a2[7] = pack2(a1.w, a1.w);
            unsigned long long b2[4];
#pragma unroll
            for (int j = 0; j < 4; j++) {
                float2 b = *(const float2*)&ws[kk][tn * 2 + 32 * j];
                b2[j] = pack2(b.x, b.y);
            }
#pragma unroll
            for (int i = 0; i < 8; i++)
#pragma unroll
                for (int j = 0; j < 4; j++)
                    asm volatile("fma.rn.f32x2 %0, %1, %2, %0;"
                                 : "+l"(acc[i][j]) : "l"(a2[i]), "l"(b2[j]));
        }
    }

#pragma unroll
    for (int j = 0; j < 4; j++) {
        int o = tn * 2 + 32 * j;
        float2 blv = *(const float2*)&bl[o];
#pragma unroll
        for (int i = 0; i < 8; i++) {
            int m = m0 + tm * 8 + i;
            if (m < N_NODES) {
                float lo, hi;
                unpack2(acc[i][j], lo, hi);
                *(__half2*)&g_hproj[(size_t)m * DIM + o] =
                    __floats2half2_rn(lo + blv.x, hi + blv.y);
            }
        }
    }
}

// ---------------- q_agg (warp per node, x2 unrolled gather) ----------------
__global__ void k_qagg_csr() {
    int node = (blockIdx.x * blockDim.x + threadIdx.x) >> 5;
    if (node >= N_NODES) return;
    int lane = threadIdx.x & 31;
    int rp0 = g_rowptr[node], rp1 = g_rowptr[node + 1];
    float4 acc = make_float4(0.f, 0.f, 0.f, 0.f);
    int j = rp0 + lane;
    for (; j + 32 < rp1; j += 64) {
        int c0 = g_cols[j];
        int c1 = g_cols[j + 32];
        float4 h0 = ((const float4*)g_hq)[c0];
        float4 h1 = ((const float4*)g_hq)[c1];
        acc.x += h0.x + h1.x; acc.y += h0.y + h1.y;
        acc.z += h0.z + h1.z; acc.w += h0.w + h1.w;
    }
    for (; j < rp1; j += 32) {
        int c = g_cols[j];
        float4 h = ((const float4*)g_hq)[c];
        acc.x += h.x; acc.y += h.y; acc.z += h.z; acc.w += h.w;
    }
#pragma unroll
    for (int off = 16; off > 0; off >>= 1) {
        acc.x += __shfl_xor_sync(0xffffffffu, acc.x, off);
        acc.y += __shfl_xor_sync(0xffffffffu, acc.y, off);
        acc.z += __shfl_xor_sync(0xffffffffu, acc.z, off);
        acc.w += __shfl_xor_sync(0xffffffffu, acc.w, off);
    }
    if (lane == 0) ((float4*)g_qagg)[node] = acc;
}

// ---------------- fused softmax + aggregation (warp per node) ----------------
__global__ __launch_bounds__(256) void k_fused(float* __restrict__ out) {
    __shared__ float4 sex[8][CAP];   // per-warp per-edge exp values (4 heads)
    __shared__ float  sal[8][CAP];   // per-warp per-edge alpha_mean

    const int w    = threadIdx.x >> 5;
    const int lane = threadIdx.x & 31;
    const int node = (blockIdx.x * blockDim.x + threadIdx.x) >> 5;
    if (node >= N_NODES) return;

    const int rp0 = g_rowptr[node], rp1 = g_rowptr[node + 1];
    const int deg = rp1 - rp0;

    float4 acc = make_float4(0.f, 0.f, 0.f, 0.f);

    if (deg > 0 && deg <= CAP) {
        const float4 kact = ((const float4*)g_kact)[node];

        // pass 1: scores -> smem, running max
        float4 m = make_float4(-INFINITY, -INFINITY, -INFINITY, -INFINITY);
        for (int jj = lane; jj < deg; jj += 32) {
            int c = __ldg(&g_cols[rp0 + jj]);
            float4 q = ((const float4*)g_qagg)[c];
            float4 s = make_float4(kact.x * q.x, kact.y * q.y,
                                   kact.z * q.z, kact.w * q.w);
            sex[w][jj] = s;
            m.x = fmaxf(m.x, s.x); m.y = fmaxf(m.y, s.y);
            m.z = fmaxf(m.z, s.z); m.w = fmaxf(m.w, s.w);
        }
#pragma unroll
        for (int off = 16; off > 0; off >>= 1) {
            m.x = fmaxf(m.x, __shfl_xor_sync(0xffffffffu, m.x, off));
            m.y = fmaxf(m.y, __shfl_xor_sync(0xffffffffu, m.y, off));
            m.z = fmaxf(m.z, __shfl_xor_sync(0xffffffffu, m.z, off));
            m.w = fmaxf(m.w, __shfl_xor_sync(0xffffffffu, m.w, off));
        }

        // pass 2: exp in smem, running sum
        float4 sum = make_float4(0.f, 0.f, 0.f, 0.f);
        for (int jj = lane; jj < deg; jj += 32) {
            float4 s = sex[w][jj];
            float4 ex = make_float4(__expf(s.x - m.x), __expf(s.y - m.y),
                                    __expf(s.z - m.z), __expf(s.w - m.w));
            sex[w][jj] = ex;
            sum.x += ex.x; sum.y += ex.y; sum.z += ex.z; sum.w += ex.w;
        }
#pragma unroll
        for (int off = 16; off > 0; off >>= 1) {
            sum.x += __shfl_xor_sync(0xffffffffu, sum.x, off);
            sum.y += __shfl_xor_sync(0xffffffffu, sum.y, off);
            sum.z += __shfl_xor_sync(0xffffffffu, sum.z, off);
            sum.w += __shfl_xor_sync(0xffffffffu, sum.w, off);
        }
        float4 inv = make_float4(0.25f / (sum.x + 1e-8f), 0.25f / (sum.y + 1e-8f),
                                 0.25f / (sum.z + 1e-8f), 0.25f / (sum.w + 1e-8f));

        // pass 2.5: alpha_mean -> smem
        for (int jj = lane; jj < deg; jj += 32) {
            float4 ex = sex[w][jj];
            sal[w][jj] = ex.x * inv.x + ex.y * inv.y + ex.z * inv.z + ex.w * inv.w;
        }
        __syncwarp();

        // pass 3: aggregate fp16 h_proj (8B per lane per edge), unrolled x8
        const __half* hp = g_hproj;
        int jj = 0;
        for (; jj + 8 <= deg; jj += 8) {
            float a[8]; int c[8];
#pragma unroll
            for (int u = 0; u < 8; u++) {
                a[u] = sal[w][jj + u];
                c[u] = __ldg(&g_cols[rp0 + jj + u]);
            }
            uint2 v[8];
#pragma unroll
            for (int u = 0; u < 8; u++)
                v[u] = *(const uint2*)&hp[(size_t)c[u] * DIM + lane * 4];
#pragma unroll
            for (int u = 0; u < 8; u++) {
                float2 f0 = __half22float2(*(const __half2*)&v[u].x);
                float2 f1 = __half22float2(*(const __half2*)&v[u].y);
                acc.x += a[u] * f0.x; acc.y += a[u] * f0.y;
                acc.z += a[u] * f1.x; acc.w += a[u] * f1.y;
            }
        }
        for (; jj < deg; jj++) {
            float a = sal[w][jj];
            int   c = __ldg(&g_cols[rp0 + jj]);
            uint2 v = *(const uint2*)&hp[(size_t)c * DIM + lane * 4];
            float2 f0 = __half22float2(*(const __half2*)&v.x);
            float2 f1 = __half22float2(*(const __half2*)&v.y);
            acc.x += a * f0.x; acc.y += a * f0.y;
            acc.z += a * f1.x; acc.w += a * f1.y;
        }
    } else if (deg > CAP) {
        // fallback (correct for any degree; effectively never taken for this graph)
        const float4 kact = ((const float4*)g_kact)[node];
        float4 m = make_float4(-INFINITY, -INFINITY, -INFINITY, -INFINITY);
        for (int j = rp0 + lane; j < rp1; j += 32) {
            int c = g_cols[j];
            float4 q = ((const float4*)g_qagg)[c];
            m.x = fmaxf(m.x, kact.x * q.x); m.y = fmaxf(m.y, kact.y * q.y);
            m.z = fmaxf(m.z, kact.z * q.z); m.w = fmaxf(m.w, kact.w * q.w);
        }
#pragma unroll
        for (int off = 16; off > 0; off >>= 1) {
            m.x = fmaxf(m.x, __shfl_xor_sync(0xffffffffu, m.x, off));
            m.y = fmaxf(m.y, __shfl_xor_sync(0xffffffffu, m.y, off));
            m.z = fmaxf(m.z, __shfl_xor_sync(0xffffffffu, m.z, off));
            m.w = fmaxf(m.w, __shfl_xor_sync(0xffffffffu, m.w, off));
        }
        float4 sum = make_float4(0.f, 0.f, 0.f, 0.f);
        for (int j = rp0 + lane; j < rp1; j += 32) {
            int c = g_cols[j];
            float4 q = ((const float4*)g_qagg)[c];
            sum.x += __expf(kact.x * q.x - m.x);
            sum.y += __expf(kact.y * q.y - m.y);
            sum.z += __expf(kact.z * q.z - m.z);
            sum.w += __expf(kact.w * q.w - m.w);
        }
#pragma unroll
        for (int off = 16; off > 0; off >>= 1) {
            sum.x += __shfl_xor_sync(0xffffffffu, sum.x, off);
            sum.y += __shfl_xor_sync(0xffffffffu, sum.y, off);
            sum.z += __shfl_xor_sync(0xffffffffu, sum.z, off);
            sum.w += __shfl_xor_sync(0xffffffffu, sum.w, off);
        }
        float4 inv = make_float4(0.25f / (sum.x + 1e-8f), 0.25f / (sum.y + 1e-8f),
                                 0.25f / (sum.z + 1e-8f), 0.25f / (sum.w + 1e-8f));
        for (int jj = 0; jj < deg; jj++) {
            int c = __ldg(&g_cols[rp0 + jj]);
            float4 q = ((const float4*)g_qagg)[c];
            float a = __expf(kact.x * q.x - m.x) * inv.x
                    + __expf(kact.y * q.y - m.y) * inv.y
                    + __expf(kact.z * q.z - m.z) * inv.z
                    + __expf(kact.w * q.w - m.w) * inv.w;
            uint2 v = *(const uint2*)&g_hproj[(size_t)c * DIM + lane * 4];
            float2 f0 = __half22float2(*(const __half2*)&v.x);
            float2 f1 = __half22float2(*(const __half2*)&v.y);
            acc.x += a * f0.x; acc.y += a * f0.y;
            acc.z += a * f1.x; acc.w += a * f1.y;
        }
    }

    acc.x = leaky_f(acc.x); acc.y = leaky_f(acc.y);
    acc.z = leaky_f(acc.z); acc.w = leaky_f(acc.w);
    *(float4*)&out[(size_t)node * DIM + lane * 4] = acc;
}

// ---------------- launch ----------------
extern "C" void kernel_launch(void* const* d_in, const int* in_sizes, int n_in,
                              void* d_out, int out_size) {
    const float* x  = (const float*)d_in[0];
    const int*   ei = (const int*)d_in[1];
    const float* Wq = (const float*)d_in[2];
    const float* Wk = (const float*)d_in[3];
    const float* Wl = (const float*)d_in[4];
    const float* bl = (const float*)d_in[5];
    float* out = (float*)d_out;

    const int TB = 256;
    const int E4_BLOCKS = (N_EDGES / 4 + TB - 1) / TB;          // 1563
    const int NODE_WARP_BLOCKS = (N_NODES * 32 + TB - 1) / TB;  // 6250

    k_zero_deg<<<(N_NODES + TB - 1) / TB, TB>>>();
    k_hist<<<E4_BLOCKS, TB>>>(ei);
    k_scan<<<1, 1024>>>();
    k_scatter<<<E4_BLOCKS, TB>>>(ei);
    k_qk<<<NODE_WARP_BLOCKS, TB>>>(x, Wq, Wk);
    k_gemm<<<(N_NODES + 127) / 128, TB>>>(x, Wl, bl);
    k_qagg_csr<<<NODE_WARP_BLOCKS, TB>>>();
    k_fused<<<NODE_WARP_BLOCKS, TB>>>(out);
}

// round 15
// speedup vs baseline: 1.0415x; 1.0063x over previous
#include <cuda_runtime.h>
#include <cuda_fp16.h>
#include <math.h>

#define N_NODES 50000
#define N_EDGES 1600000
#define DIM     128
#define NHEADS  4
#define NEG_SLOPE 0.2f
#define CAP     128   // smem fast-path neighbor cap (Poisson(32) max deg ~70)

// ---------------- scratch (static device arrays; no allocation) ----------------
__device__ int    g_deg   [N_NODES];
__device__ int    g_rowptr[N_NODES + 1];
__device__ int    g_cursor[N_NODES];
__device__ int    g_cols  [N_EDGES];
__device__ float  g_hq    [N_NODES * NHEADS];
__device__ float  g_kact  [N_NODES * NHEADS];
__device__ float  g_qagg  [N_NODES * NHEADS];
__device__ __half g_hproj [(size_t)N_NODES * DIM];   // fp16 value matrix (halves gather bytes)

// ---------------- helpers ----------------
static __device__ __forceinline__ float leaky_f(float v) {
    return v >= 0.f ? v : NEG_SLOPE * v;
}
static __device__ __forceinline__ unsigned long long pack2(float lo, float hi) {
    unsigned long long r;
    asm("mov.b64 %0, {%1,%2};" : "=l"(r) : "f"(lo), "f"(hi));
    return r;
}
static __device__ __forceinline__ void unpack2(unsigned long long v, float& lo, float& hi) {
    asm("mov.b64 {%0,%1}, %2;" : "=f"(lo), "=f"(hi) : "l"(v));
}

// ---------------- CSR build ----------------

// NOTE: g_deg is zero at process start (static zero-init) and is re-zeroed by
// k_scatter at the end of every execution, so every launch sees zeroed counters.
__global__ void k_hist(const int* __restrict__ ei) {
    int t = blockIdx.x * blockDim.x + threadIdx.x;
    int base = t * 4;
    if (base >= N_EDGES) return;
    int4 r = *(const int4*)&ei[base];
    atomicAdd(&g_deg[r.x], 1);
    atomicAdd(&g_deg[r.y], 1);
    atomicAdd(&g_deg[r.z], 1);
    atomicAdd(&g_deg[r.w], 1);
}

__global__ __launch_bounds__(1024) void k_scan() {
    __shared__ int sh[1024];
    const int T = 1024;
    const int per = (N_NODES + T - 1) / T;
    int t = threadIdx.x;
    int base = t * per;
    int s = 0;
    for (int i = 0; i < per; i++) {
        int idx = base + i;
        if (idx < N_NODES) s += g_deg[idx];
    }
    sh[t] = s;
    __syncthreads();
    for (int off = 1; off < T; off <<= 1) {
        int v = (t >= off) ? sh[t - off] : 0;
        __syncthreads();
        sh[t] += v;
        __syncthreads();
    }
    int run = (t == 0) ? 0 : sh[t - 1];
    for (int i = 0; i < per; i++) {
        int idx = base + i;
        if (idx < N_NODES) {
            g_rowptr[idx] = run;
            g_cursor[idx] = run;
            run += g_deg[idx];
        }
    }
    if (t == T - 1) g_rowptr[N_NODES] = run;
}

// scatter cols into CSR order; also re-zero g_deg for the next replay
// (deg is dead after k_scan; rowptr carries the information from here on).
__global__ void k_scatter(const int* __restrict__ ei) {
    int t = blockIdx.x * blockDim.x + threadIdx.x;
    if (t < N_NODES) g_deg[t] = 0;
    int base = t * 4;
    if (base >= N_EDGES) return;
    int4 r = *(const int4*)&ei[base];
    int4 c = *(const int4*)&ei[N_EDGES + base];
    int p0 = atomicAdd(&g_cursor[r.x], 1);
    int p1 = atomicAdd(&g_cursor[r.y], 1);
    int p2 = atomicAdd(&g_cursor[r.z], 1);
    int p3 = atomicAdd(&g_cursor[r.w], 1);
    g_cols[p0] = c.x;
    g_cols[p1] = c.y;
    g_cols[p2] = c.z;
    g_cols[p3] = c.w;
}

// ---------------- projections ----------------

__global__ void k_qk(const float* __restrict__ x,
                     const float* __restrict__ Wq,
                     const float* __restrict__ Wk) {
    int warp = (blockIdx.x * blockDim.x + threadIdx.x) >> 5;
    if (warp >= N_NODES) return;
    int lane = threadIdx.x & 31;

    float4 xv = *(const float4*)&x[(size_t)warp * DIM + lane * 4];
    float q[NHEADS], k[NHEADS];
#pragma unroll
    for (int h = 0; h < NHEADS; h++) {
        float4 wq = *(const float4*)&Wq[h * DIM + lane * 4];
        float4 wk = *(const float4*)&Wk[h * DIM + lane * 4];
        q[h] = xv.x * wq.x + xv.y * wq.y + xv.z * wq.z + xv.w * wq.w;
        k[h] = xv.x * wk.x + xv.y * wk.y + xv.z * wk.z + xv.w * wk.w;
    }
#pragma unroll
    for (int off = 16; off > 0; off >>= 1) {
#pragma unroll
        for (int h = 0; h < NHEADS; h++) {
            q[h] += __shfl_xor_sync(0xffffffffu, q[h], off);
            k[h] += __shfl_xor_sync(0xffffffffu, k[h], off);
        }
    }
    if (lane == 0) {
#pragma unroll
        for (int h = 0; h < NHEADS; h++) {
            g_hq[warp * NHEADS + h]   = q[h];
            g_kact[warp * NHEADS + h] = leaky_f(k[h]);
        }
    }
}

__global__ __launch_bounds__(256) void k_gemm(const float* __restrict__ x,
                                              const float* __restrict__ Wl,
                                              const float* __restrict__ bl) {
    __shared__ float xs[32][DIM];
    __shared__ float ws[32][DIM];

    const int tid = threadIdx.x;
    const int tm = tid >> 4;
    const int tn = tid & 15;
    const int m0 = blockIdx.x * 128;

    unsigned long long acc[8][4];
#pragma unroll
    for (int i = 0; i < 8; i++)
#pragma unroll
        for (int j = 0; j < 4; j++) acc[i][j] = 0ull;

    const int lrow = tid >> 1;
    const int lk   = (tid & 1) * 16;

    for (int k0 = 0; k0 < DIM; k0 += 32) {
        __syncthreads();
        {
            int gm = m0 + lrow;
#pragma unroll
            for (int q = 0; q < 16; q += 4) {
                float4 v = make_float4(0.f, 0.f, 0.f, 0.f);
                if (gm < N_NODES)
                    v = *(const float4*)&x[(size_t)gm * DIM + k0 + lk + q];
                xs[lk + q + 0][lrow] = v.x;
                xs[lk + q + 1][lrow] = v.y;
                xs[lk + q + 2][lrow] = v.z;
                xs[lk + q + 3][lrow] = v.w;
            }
        }
        {
#pragma unroll
            for (int q = 0; q < 16; q += 4) {
                float4 w = *(const float4*)&Wl[(size_t)lrow * DIM + k0 + lk + q];
                ws[lk + q + 0][lrow] = w.x;
                ws[lk + q + 1][lrow] = w.y;
                ws[lk + q + 2][lrow] = w.z;
                ws[lk + q + 3][lrow] = w.w;
            }
        }
        __syncthreads();

#pragma unroll 8
        for (int kk = 0; kk < 32; kk++) {
            float4 a0 = *(const float4*)&xs[kk][tm * 8];
            float4 a1 = *(const float4*)&xs[kk][tm * 8 + 4];
            unsigned long long a2[8];
            a2[0] = pack2(a0.x, a0.x); a2[1] = pack2(a0.y, a0.y);
            a2[2] = pack2(a0.z, a0.z); a2[3] = pack2(a0.w, a0.w);
            a2[4] = pack2(a1.x, a1.x); a2[5] = pack2(a1.y, a1.y);
            a2[6] = pack2(a1.z, a1.z); a2[7] = pack2(a1.w, a1.w);
            unsigned long long b2[4];
#pragma unroll
            for (int j = 0; j < 4; j++) {
                float2 b = *(const float2*)&ws[kk][tn * 2 + 32 * j];
                b2[j] = pack2(b.x, b.y);
            }
#pragma unroll
            for (int i = 0; i < 8; i++)
#pragma unroll
                for (int j = 0; j < 4; j++)
                    asm volatile("fma.rn.f32x2 %0, %1, %2, %0;"
                                 : "+l"(acc[i][j]) : "l"(a2[i]), "l"(b2[j]));
        }
    }

#pragma unroll
    for (int j = 0; j < 4; j++) {
        int o = tn * 2 + 32 * j;
        float2 blv = *(const float2*)&bl[o];
#pragma unroll
        for (int i = 0; i < 8; i++) {
            int m = m0 + tm * 8 + i;
            if (m < N_NODES) {
                float lo, hi;
                unpack2(acc[i][j], lo, hi);
                *(__half2*)&g_hproj[(size_t)m * DIM + o] =
                    __floats2half2_rn(lo + blv.x, hi + blv.y);
            }
        }
    }
}

// ---------------- q_agg (warp per node, x2 unrolled gather) ----------------
__global__ void k_qagg_csr() {
    int node = (blockIdx.x * blockDim.x + threadIdx.x) >> 5;
    if (node >= N_NODES) return;
    int lane = threadIdx.x & 31;
    int rp0 = g_rowptr[node], rp1 = g_rowptr[node + 1];
    float4 acc = make_float4(0.f, 0.f, 0.f, 0.f);
    int j = rp0 + lane;
    for (; j + 32 < rp1; j += 64) {
        int c0 = g_cols[j];
        int c1 = g_cols[j + 32];
        float4 h0 = ((const float4*)g_hq)[c0];
        float4 h1 = ((const float4*)g_hq)[c1];
        acc.x += h0.x + h1.x; acc.y += h0.y + h1.y;
        acc.z += h0.z + h1.z; acc.w += h0.w + h1.w;
    }
    for (; j < rp1; j += 32) {
        int c = g_cols[j];
        float4 h = ((const float4*)g_hq)[c];
        acc.x += h.x; acc.y += h.y; acc.z += h.z; acc.w += h.w;
    }
#pragma unroll
    for (int off = 16; off > 0; off >>= 1) {
        acc.x += __shfl_xor_sync(0xffffffffu, acc.x, off);
        acc.y += __shfl_xor_sync(0xffffffffu, acc.y, off);
        acc.z += __shfl_xor_sync(0xffffffffu, acc.z, off);
        acc.w += __shfl_xor_sync(0xffffffffu, acc.w, off);
    }
    if (lane == 0) ((float4*)g_qagg)[node] = acc;
}

// ---------------- fused softmax + aggregation (warp per node) ----------------
__global__ __launch_bounds__(256) void k_fused(float* __restrict__ out) {
    __shared__ float4 sex[8][CAP];   // per-warp per-edge exp values (4 heads)
    __shared__ float  sal[8][CAP];   // per-warp per-edge alpha_mean

    const int w    = threadIdx.x >> 5;
    const int lane = threadIdx.x & 31;
    const int node = (blockIdx.x * blockDim.x + threadIdx.x) >> 5;
    if (node >= N_NODES) return;

    const int rp0 = g_rowptr[node], rp1 = g_rowptr[node + 1];
    const int deg = rp1 - rp0;

    float4 acc = make_float4(0.f, 0.f, 0.f, 0.f);

    if (deg > 0 && deg <= CAP) {
        const float4 kact = ((const float4*)g_kact)[node];

        // pass 1: scores -> smem, running max
        float4 m = make_float4(-INFINITY, -INFINITY, -INFINITY, -INFINITY);
        for (int jj = lane; jj < deg; jj += 32) {
            int c = __ldg(&g_cols[rp0 + jj]);
            float4 q = ((const float4*)g_qagg)[c];
            float4 s = make_float4(kact.x * q.x, kact.y * q.y,
                                   kact.z * q.z, kact.w * q.w);
            sex[w][jj] = s;
            m.x = fmaxf(m.x, s.x); m.y = fmaxf(m.y, s.y);
            m.z = fmaxf(m.z, s.z); m.w = fmaxf(m.w, s.w);
        }
#pragma unroll
        for (int off = 16; off > 0; off >>= 1) {
            m.x = fmaxf(m.x, __shfl_xor_sync(0xffffffffu, m.x, off));
            m.y = fmaxf(m.y, __shfl_xor_sync(0xffffffffu, m.y, off));
            m.z = fmaxf(m.z, __shfl_xor_sync(0xffffffffu, m.z, off));
            m.w = fmaxf(m.w, __shfl_xor_sync(0xffffffffu, m.w, off));
        }

        // pass 2: exp in smem, running sum
        float4 sum = make_float4(0.f, 0.f, 0.f, 0.f);
        for (int jj = lane; jj < deg; jj += 32) {
            float4 s = sex[w][jj];
            float4 ex = make_float4(__expf(s.x - m.x), __expf(s.y - m.y),
                                    __expf(s.z - m.z), __expf(s.w - m.w));
            sex[w][jj] = ex;
            sum.x += ex.x; sum.y += ex.y; sum.z += ex.z; sum.w += ex.w;
        }
#pragma unroll
        for (int off = 16; off > 0; off >>= 1) {
            sum.x += __shfl_xor_sync(0xffffffffu, sum.x, off);
            sum.y += __shfl_xor_sync(0xffffffffu, sum.y, off);
            sum.z += __shfl_xor_sync(0xffffffffu, sum.z, off);
            sum.w += __shfl_xor_sync(0xffffffffu, sum.w, off);
        }
        float4 inv = make_float4(0.25f / (sum.x + 1e-8f), 0.25f / (sum.y + 1e-8f),
                                 0.25f / (sum.z + 1e-8f), 0.25f / (sum.w + 1e-8f));

        // pass 2.5: alpha_mean -> smem
        for (int jj = lane; jj < deg; jj += 32) {
            float4 ex = sex[w][jj];
            sal[w][jj] = ex.x * inv.x + ex.y * inv.y + ex.z * inv.z + ex.w * inv.w;
        }
        __syncwarp();

        // pass 3: aggregate fp16 h_proj (8B per lane per edge), unrolled x8
        const __half* hp = g_hproj;
        int jj = 0;
        for (; jj + 8 <= deg; jj += 8) {
            float a[8]; int c[8];
#pragma unroll
            for (int u = 0; u < 8; u++) {
                a[u] = sal[w][jj + u];
                c[u] = __ldg(&g_cols[rp0 + jj + u]);
            }
            uint2 v[8];
#pragma unroll
            for (int u = 0; u < 8; u++)
                v[u] = *(const uint2*)&hp[(size_t)c[u] * DIM + lane * 4];
#pragma unroll
            for (int u = 0; u < 8; u++) {
                float2 f0 = __half22float2(*(const __half2*)&v[u].x);
                float2 f1 = __half22float2(*(const __half2*)&v[u].y);
                acc.x += a[u] * f0.x; acc.y += a[u] * f0.y;
                acc.z += a[u] * f1.x; acc.w += a[u] * f1.y;
            }
        }
        for (; jj < deg; jj++) {
            float a = sal[w][jj];
            int   c = __ldg(&g_cols[rp0 + jj]);
            uint2 v = *(const uint2*)&hp[(size_t)c * DIM + lane * 4];
            float2 f0 = __half22float2(*(const __half2*)&v.x);
            float2 f1 = __half22float2(*(const __half2*)&v.y);
            acc.x += a * f0.x; acc.y += a * f0.y;
            acc.z += a * f1.x; acc.w += a * f1.y;
        }
    } else if (deg > CAP) {
        // fallback (correct for any degree; effectively never taken for this graph)
        const float4 kact = ((const float4*)g_kact)[node];
        float4 m = make_float4(-INFINITY, -INFINITY, -INFINITY, -INFINITY);
        for (int j = rp0 + lane; j < rp1; j += 32) {
            int c = g_cols[j];
            float4 q = ((const float4*)g_qagg)[c];
            m.x = fmaxf(m.x, kact.x * q.x); m.y = fmaxf(m.y, kact.y * q.y);
            m.z = fmaxf(m.z, kact.z * q.z); m.w = fmaxf(m.w, kact.w * q.w);
        }
#pragma unroll
        for (int off = 16; off > 0; off >>= 1) {
            m.x = fmaxf(m.x, __shfl_xor_sync(0xffffffffu, m.x, off));
            m.y = fmaxf(m.y, __shfl_xor_sync(0xffffffffu, m.y, off));
            m.z = fmaxf(m.z, __shfl_xor_sync(0xffffffffu, m.z, off));
            m.w = fmaxf(m.w, __shfl_xor_sync(0xffffffffu, m.w, off));
        }
        float4 sum = make_float4(0.f, 0.f, 0.f, 0.f);
        for (int j = rp0 + lane; j < rp1; j += 32) {
            int c = g_cols[j];
            float4 q = ((const float4*)g_qagg)[c];
            sum.x += __expf(kact.x * q.x - m.x);
            sum.y += __expf(kact.y * q.y - m.y);
            sum.z += __expf(kact.z * q.z - m.z);
            sum.w += __expf(kact.w * q.w - m.w);
        }
#pragma unroll
        for (int off = 16; off > 0; off >>= 1) {
            sum.x += __shfl_xor_sync(0xffffffffu, sum.x, off);
            sum.y += __shfl_xor_sync(0xffffffffu, sum.y, off);
            sum.z += __shfl_xor_sync(0xffffffffu, sum.z, off);
            sum.w += __shfl_xor_sync(0xffffffffu, sum.w, off);
        }
        float4 inv = make_float4(0.25f / (sum.x + 1e-8f), 0.25f / (sum.y + 1e-8f),
                                 0.25f / (sum.z + 1e-8f), 0.25f / (sum.w + 1e-8f));
        for (int jj = 0; jj < deg; jj++) {
            int c = __ldg(&g_cols[rp0 + jj]);
            float4 q = ((const float4*)g_qagg)[c];
            float a = __expf(kact.x * q.x - m.x) * inv.x
                    + __expf(kact.y * q.y - m.y) * inv.y
                    + __expf(kact.z * q.z - m.z) * inv.z
                    + __expf(kact.w * q.w - m.w) * inv.w;
            uint2 v = *(const uint2*)&g_hproj[(size_t)c * DIM + lane * 4];
            float2 f0 = __half22float2(*(const __half2*)&v.x);
            float2 f1 = __half22float2(*(const __half2*)&v.y);
            acc.x += a * f0.x; acc.y += a * f0.y;
            acc.z += a * f1.x; acc.w += a * f1.y;
        }
    }

    acc.x = leaky_f(acc.x); acc.y = leaky_f(acc.y);
    acc.z = leaky_f(acc.z); acc.w = leaky_f(acc.w);
    *(float4*)&out[(size_t)node * DIM + lane * 4] = acc;
}

// ---------------- launch (forked capture graph: CSR chain || projections) ----------------
extern "C" void kernel_launch(void* const* d_in, const int* in_sizes, int n_in,
                              void* d_out, int out_size) {
    const float* x  = (const float*)d_in[0];
    const int*   ei = (const int*)d_in[1];
    const float* Wq = (const float*)d_in[2];
    const float* Wk = (const float*)d_in[3];
    const float* Wl = (const float*)d_in[4];
    const float* bl = (const float*)d_in[5];
    float* out = (float*)d_out;

    const int TB = 256;
    const int E4_BLOCKS = (N_EDGES / 4 + TB - 1) / TB;          // 1563
    const int NODE_WARP_BLOCKS = (N_NODES * 32 + TB - 1) / TB;  // 6250

    // host-side resources, created once (host allocations only; no device memory)
    static cudaStream_t s1 = nullptr;
    static cudaEvent_t evFork = nullptr, evQk = nullptr, evGemm = nullptr;
    static bool streams_ok = false;
    if (!s1) {
        streams_ok =
            (cudaStreamCreateWithFlags(&s1, cudaStreamNonBlocking) == cudaSuccess) &&
            (cudaEventCreateWithFlags(&evFork, cudaEventDisableTiming) == cudaSuccess) &&
            (cudaEventCreateWithFlags(&evQk,   cudaEventDisableTiming) == cudaSuccess) &&
            (cudaEventCreateWithFlags(&evGemm, cudaEventDisableTiming) == cudaSuccess);
    }

    if (streams_ok) {
        // fork: projections on s1, CSR build on the (captured) legacy stream
        cudaEventRecord(evFork, 0);
        cudaStreamWaitEvent(s1, evFork, 0);

        k_qk<<<NODE_WARP_BLOCKS, TB, 0, s1>>>(x, Wq, Wk);
        cudaEventRecord(evQk, s1);
        k_gemm<<<(N_NODES + 127) / 128, TB, 0, s1>>>(x, Wl, bl);
        cudaEventRecord(evGemm, s1);

        k_hist<<<E4_BLOCKS, TB>>>(ei);
        k_scan<<<1, 1024>>>();
        k_scatter<<<E4_BLOCKS, TB>>>(ei);

        cudaStreamWaitEvent(0, evQk, 0);     // qagg needs qk + scatter
        k_qagg_csr<<<NODE_WARP_BLOCKS, TB>>>();
        cudaStreamWaitEvent(0, evGemm, 0);   // fused needs qagg + gemm (joins s1)
        k_fused<<<NODE_WARP_BLOCKS, TB>>>(out);
    } else {
        // serial fallback
        k_hist<<<E4_BLOCKS, TB>>>(ei);
        k_scan<<<1, 1024>>>();
        k_scatter<<<E4_BLOCKS, TB>>>(ei);
        k_qk<<<NODE_WARP_BLOCKS, TB>>>(x, Wq, Wk);
        k_gemm<<<(N_NODES + 127) / 128, TB>>>(x, Wl, bl);
        k_qagg_csr<<<NODE_WARP_BLOCKS, TB>>>();
        k_fused<<<NODE_WARP_BLOCKS, TB>>>(out);
    }
}

// round 16
// speedup vs baseline: 1.3968x; 1.3412x over previous
#include <cuda_runtime.h>
#include <cuda_fp16.h>
#include <math.h>

#define N_NODES 50000
#define N_EDGES 1600000
#define DIM     128
#define NHEADS  4
#define NEG_SLOPE 0.2f
#define CAP     128   // smem fast-path neighbor cap (Poisson(32) max deg ~70)

// scan layout: 1024 threads x 52 elements (13 int4) = 53248 >= N_NODES
#define SCAN_T   1024
#define SCAN_V   13
#define SCAN_PER (SCAN_V * 4)            // 52
#define SCAN_PAD (SCAN_T * SCAN_PER)     // 53248

// ---------------- scratch (static device arrays; no allocation) ----------------
// g_deg padded: entries >= N_NODES are never written (node ids < N_NODES) and are
// zero from static init, so the padded scan reads zeros there.
__device__ int    g_deg   [SCAN_PAD];
__device__ int    g_rowptr[SCAN_PAD];    // rowptr[N_NODES] == N_EDGES lands inside
__device__ int    g_cursor[SCAN_PAD];
__device__ int    g_cols  [N_EDGES];
__device__ float  g_hq    [N_NODES * NHEADS];
__device__ float  g_kact  [N_NODES * NHEADS];
__device__ float  g_qagg  [N_NODES * NHEADS];
__device__ __half g_hproj [(size_t)N_NODES * DIM];   // fp16 value matrix

// ---------------- helpers ----------------
static __device__ __forceinline__ float leaky_f(float v) {
    return v >= 0.f ? v : NEG_SLOPE * v;
}
static __device__ __forceinline__ unsigned long long pack2(float lo, float hi) {
    unsigned long long r;
    asm("mov.b64 %0, {%1,%2};" : "=l"(r) : "f"(lo), "f"(hi));
    return r;
}
static __device__ __forceinline__ void unpack2(unsigned long long v, float& lo, float& hi) {
    asm("mov.b64 {%0,%1}, %2;" : "=f"(lo), "=f"(hi) : "l"(v));
}

// ---------------- CSR build ----------------

// g_deg is zero at process start and re-zeroed by k_scatter each execution.
__global__ void k_hist(const int* __restrict__ ei) {
    int t = blockIdx.x * blockDim.x + threadIdx.x;
    int base = t * 4;
    if (base >= N_EDGES) return;
    int4 r = *(const int4*)&ei[base];
    atomicAdd(&g_deg[r.x], 1);
    atomicAdd(&g_deg[r.y], 1);
    atomicAdd(&g_deg[r.z], 1);
    atomicAdd(&g_deg[r.w], 1);
}

// single-block scan, MLP-batched: 13 independent int4 loads per thread per pass.
__global__ __launch_bounds__(SCAN_T) void k_scan() {
    __shared__ int sh[SCAN_T];
    const int t = threadIdx.x;
    const int4* deg4 = (const int4*)g_deg;

    // pass 1: per-thread segment sum (13 independent LDG.128)
    int s = 0;
#pragma unroll
    for (int i = 0; i < SCAN_V; i++) {
        int4 d = deg4[t * SCAN_V + i];
        s += d.x + d.y + d.z + d.w;
    }
    sh[t] = s;
    __syncthreads();

    // Kogge-Stone block scan (inclusive)
    for (int off = 1; off < SCAN_T; off <<= 1) {
        int v = (t >= off) ? sh[t - off] : 0;
        __syncthreads();
        sh[t] += v;
        __syncthreads();
    }
    int run = (t == 0) ? 0 : sh[t - 1];

    // pass 2: re-load (L1/L2 hits, independent), prefix in registers, int4 stores
    int4* rp4 = (int4*)g_rowptr;
    int4* cu4 = (int4*)g_cursor;
#pragma unroll
    for (int i = 0; i < SCAN_V; i++) {
        int4 d = deg4[t * SCAN_V + i];
        int4 o;
        o.x = run; run += d.x;
        o.y = run; run += d.y;
        o.z = run; run += d.z;
        o.w = run; run += d.w;
        rp4[t * SCAN_V + i] = o;
        cu4[t * SCAN_V + i] = o;
    }
}

// scatter cols into CSR order; also re-zero g_deg for the next replay.
__global__ void k_scatter(const int* __restrict__ ei) {
    int t = blockIdx.x * blockDim.x + threadIdx.x;
    if (t < N_NODES) g_deg[t] = 0;
    int base = t * 4;
    if (base >= N_EDGES) return;
    int4 r = *(const int4*)&ei[base];
    int4 c = *(const int4*)&ei[N_EDGES + base];
    int p0 = atomicAdd(&g_cursor[r.x], 1);
    int p1 = atomicAdd(&g_cursor[r.y], 1);
    int p2 = atomicAdd(&g_cursor[r.z], 1);
    int p3 = atomicAdd(&g_cursor[r.w], 1);
    g_cols[p0] = c.x;
    g_cols[p1] = c.y;
    g_cols[p2] = c.z;
    g_cols[p3] = c.w;
}

// ---------------- projections ----------------

__global__ void k_qk(const float* __restrict__ x,
                     const float* __restrict__ Wq,
                     const float* __restrict__ Wk) {
    int warp = (blockIdx.x * blockDim.x + threadIdx.x) >> 5;
    if (warp >= N_NODES) return;
    int lane = threadIdx.x & 31;

    float4 xv = *(const float4*)&x[(size_t)warp * DIM + lane * 4];
    float q[NHEADS], k[NHEADS];
#pragma unroll
    for (int h = 0; h < NHEADS; h++) {
        float4 wq = *(const float4*)&Wq[h * DIM + lane * 4];
        float4 wk = *(const float4*)&Wk[h * DIM + lane * 4];
        q[h] = xv.x * wq.x + xv.y * wq.y + xv.z * wq.z + xv.w * wq.w;
        k[h] = xv.x * wk.x + xv.y * wk.y + xv.z * wk.z + xv.w * wk.w;
    }
#pragma unroll
    for (int off = 16; off > 0; off >>= 1) {
#pragma unroll
        for (int h = 0; h < NHEADS; h++) {
            q[h] += __shfl_xor_sync(0xffffffffu, q[h], off);
            k[h] += __shfl_xor_sync(0xffffffffu, k[h], off);
        }
    }
    if (lane == 0) {
#pragma unroll
        for (int h = 0; h < NHEADS; h++) {
            g_hq[warp * NHEADS + h]   = q[h];
            g_kact[warp * NHEADS + h] = leaky_f(k[h]);
        }
    }
}

__global__ __launch_bounds__(256) void k_gemm(const float* __restrict__ x,
                                              const float* __restrict__ Wl,
                                              const float* __restrict__ bl) {
    __shared__ float xs[32][DIM];
    __shared__ float ws[32][DIM];

    const int tid = threadIdx.x;
    const int tm = tid >> 4;
    const int tn = tid & 15;
    const int m0 = blockIdx.x * 128;

    unsigned long long acc[8][4];
#pragma unroll
    for (int i = 0; i < 8; i++)
#pragma unroll
        for (int j = 0; j < 4; j++) acc[i][j] = 0ull;

    const int lrow = tid >> 1;
    const int lk   = (tid & 1) * 16;

    for (int k0 = 0; k0 < DIM; k0 += 32) {
        __syncthreads();
        {
            int gm = m0 + lrow;
#pragma unroll
            for (int q = 0; q < 16; q += 4) {
                float4 v = make_float4(0.f, 0.f, 0.f, 0.f);
                if (gm < N_NODES)
                    v = *(const float4*)&x[(size_t)gm * DIM + k0 + lk + q];
                xs[lk + q + 0][lrow] = v.x;
                xs[lk + q + 1][lrow] = v.y;
                xs[lk + q + 2][lrow] = v.z;
                xs[lk + q + 3][lrow] = v.w;
            }
        }
        {
#pragma unroll
            for (int q = 0; q < 16; q += 4) {
                float4 w = *(const float4*)&Wl[(size_t)lrow * DIM + k0 + lk + q];
                ws[lk + q + 0][lrow] = w.x;
                ws[lk + q + 1][lrow] = w.y;
                ws[lk + q + 2][lrow] = w.z;
                ws[lk + q + 3][lrow] = w.w;
            }
        }
        __syncthreads();

#pragma unroll 8
        for (int kk = 0; kk < 32; kk++) {
            float4 a0 = *(const float4*)&xs[kk][tm * 8];
            float4 a1 = *(const float4*)&xs[kk][tm * 8 + 4];
            unsigned long long a2[8];
            a2[0] = pack2(a0.x, a0.x); a2[1] = pack2(a0.y, a0.y);
            a2[2] = pack2(a0.z, a0.z); a2[3] = pack2(a0.w, a0.w);
            a2[4] = pack2(a1.x, a1.x); a2[5] = pack2(a1.y, a1.y);
            a2[6] = pack2(a1.z, a1.z); a2[7] = pack2(a1.w, a1.w);
            unsigned long long b2[4];
#pragma unroll
            for (int j = 0; j < 4; j++) {
                float2 b = *(const float2*)&ws[kk][tn * 2 + 32 * j];
                b2[j] = pack2(b.x, b.y);
            }
#pragma unroll
            for (int i = 0; i < 8; i++)
#pragma unroll
                for (int j = 0; j < 4; j++)
                    asm volatile("fma.rn.f32x2 %0, %1, %2, %0;"
                                 : "+l"(acc[i][j]) : "l"(a2[i]), "l"(b2[j]));
        }
    }

#pragma unroll
    for (int j = 0; j < 4; j++) {
        int o = tn * 2 + 32 * j;
        float2 blv = *(const float2*)&bl[o];
#pragma unroll
        for (int i = 0; i < 8; i++) {
            int m = m0 + tm * 8 + i;
            if (m < N_NODES) {
                float lo, hi;
                unpack2(acc[i][j], lo, hi);
                *(__half2*)&g_hproj[(size_t)m * DIM + o] =
                    __floats2half2_rn(lo + blv.x, hi + blv.y);
            }
        }
    }
}

// ---------------- q_agg (warp per node, x2 unrolled gather) ----------------
__global__ void k_qagg_csr() {
    int node = (blockIdx.x * blockDim.x + threadIdx.x) >> 5;
    if (node >= N_NODES) return;
    int lane = threadIdx.x & 31;
    int rp0 = g_rowptr[node], rp1 = g_rowptr[node + 1];
    float4 acc = make_float4(0.f, 0.f, 0.f, 0.f);
    int j = rp0 + lane;
    for (; j + 32 < rp1; j += 64) {
        int c0 = g_cols[j];
        int c1 = g_cols[j + 32];
        float4 h0 = ((const float4*)g_hq)[c0];
        float4 h1 = ((const float4*)g_hq)[c1];
        acc.x += h0.x + h1.x; acc.y += h0.y + h1.y;
        acc.z += h0.z + h1.z; acc.w += h0.w + h1.w;
    }
    for (; j < rp1; j += 32) {
        int c = g_cols[j];
        float4 h = ((const float4*)g_hq)[c];
        acc.x += h.x; acc.y += h.y; acc.z += h.z; acc.w += h.w;
    }
#pragma unroll
    for (int off = 16; off > 0; off >>= 1) {
        acc.x += __shfl_xor_sync(0xffffffffu, acc.x, off);
        acc.y += __shfl_xor_sync(0xffffffffu, acc.y, off);
        acc.z += __shfl_xor_sync(0xffffffffu, acc.z, off);
        acc.w += __shfl_xor_sync(0xffffffffu, acc.w, off);
    }
    if (lane == 0) ((float4*)g_qagg)[node] = acc;
}

// ---------------- fused softmax + aggregation (warp per node) ----------------
__global__ __launch_bounds__(256) void k_fused(float* __restrict__ out) {
    __shared__ float4 sex[8][CAP];   // per-warp per-edge exp values (4 heads)
    __shared__ float  sal[8][CAP];   // per-warp per-edge alpha_mean

    const int w    = threadIdx.x >> 5;
    const int lane = threadIdx.x & 31;
    const int node = (blockIdx.x * blockDim.x + threadIdx.x) >> 5;
    if (node >= N_NODES) return;

    const int rp0 = g_rowptr[node], rp1 = g_rowptr[node + 1];
    const int deg = rp1 - rp0;

    float4 acc = make_float4(0.f, 0.f, 0.f, 0.f);

    if (deg > 0 && deg <= CAP) {
        const float4 kact = ((const float4*)g_kact)[node];

        // pass 1: scores -> smem, running max
        float4 m = make_float4(-INFINITY, -INFINITY, -INFINITY, -INFINITY);
        for (int jj = lane; jj < deg; jj += 32) {
            int c = __ldg(&g_cols[rp0 + jj]);
            float4 q = ((const float4*)g_qagg)[c];
            float4 s = make_float4(kact.x * q.x, kact.y * q.y,
                                   kact.z * q.z, kact.w * q.w);
            sex[w][jj] = s;
            m.x = fmaxf(m.x, s.x); m.y = fmaxf(m.y, s.y);
            m.z = fmaxf(m.z, s.z); m.w = fmaxf(m.w, s.w);
        }
#pragma unroll
        for (int off = 16; off > 0; off >>= 1) {
            m.x = fmaxf(m.x, __shfl_xor_sync(0xffffffffu, m.x, off));
            m.y = fmaxf(m.y, __shfl_xor_sync(0xffffffffu, m.y, off));
            m.z = fmaxf(m.z, __shfl_xor_sync(0xffffffffu, m.z, off));
            m.w = fmaxf(m.w, __shfl_xor_sync(0xffffffffu, m.w, off));
        }

        // pass 2: exp in smem, running sum
        float4 sum = make_float4(0.f, 0.f, 0.f, 0.f);
        for (int jj = lane; jj < deg; jj += 32) {
            float4 s = sex[w][jj];
            float4 ex = make_float4(__expf(s.x - m.x), __expf(s.y - m.y),
                                    __expf(s.z - m.z), __expf(s.w - m.w));
            sex[w][jj] = ex;
            sum.x += ex.x; sum.y += ex.y; sum.z += ex.z; sum.w += ex.w;
        }
#pragma unroll
        for (int off = 16; off > 0; off >>= 1) {
            sum.x += __shfl_xor_sync(0xffffffffu, sum.x, off);
            sum.y += __shfl_xor_sync(0xffffffffu, sum.y, off);
            sum.z += __shfl_xor_sync(0xffffffffu, sum.z, off);
            sum.w += __shfl_xor_sync(0xffffffffu, sum.w, off);
        }
        float4 inv = make_float4(0.25f / (sum.x + 1e-8f), 0.25f / (sum.y + 1e-8f),
                                 0.25f / (sum.z + 1e-8f), 0.25f / (sum.w + 1e-8f));

        // pass 2.5: alpha_mean -> smem
        for (int jj = lane; jj < deg; jj += 32) {
            float4 ex = sex[w][jj];
            sal[w][jj] = ex.x * inv.x + ex.y * inv.y + ex.z * inv.z + ex.w * inv.w;
        }
        __syncwarp();

        // pass 3: aggregate fp16 h_proj (8B per lane per edge), unrolled x8
        const __half* hp = g_hproj;
        int jj = 0;
        for (; jj + 8 <= deg; jj += 8) {
            float a[8]; int c[8];
#pragma unroll
            for (int u = 0; u < 8; u++) {
                a[u] = sal[w][jj + u];
                c[u] = __ldg(&g_cols[rp0 + jj + u]);
            }
            uint2 v[8];
#pragma unroll
            for (int u = 0; u < 8; u++)
                v[u] = *(const uint2*)&hp[(size_t)c[u] * DIM + lane * 4];
#pragma unroll
            for (int u = 0; u < 8; u++) {
                float2 f0 = __half22float2(*(const __half2*)&v[u].x);
                float2 f1 = __half22float2(*(const __half2*)&v[u].y);
                acc.x += a[u] * f0.x; acc.y += a[u] * f0.y;
                acc.z += a[u] * f1.x; acc.w += a[u] * f1.y;
            }
        }
        for (; jj < deg; jj++) {
            float a = sal[w][jj];
            int   c = __ldg(&g_cols[rp0 + jj]);
            uint2 v = *(const uint2*)&hp[(size_t)c * DIM + lane * 4];
            float2 f0 = __half22float2(*(const __half2*)&v.x);
            float2 f1 = __half22float2(*(const __half2*)&v.y);
            acc.x += a * f0.x; acc.y += a * f0.y;
            acc.z += a * f1.x; acc.w += a * f1.y;
        }
    } else if (deg > CAP) {
        // fallback (correct for any degree; effectively never taken for this graph)
        const float4 kact = ((const float4*)g_kact)[node];
        float4 m = make_float4(-INFINITY, -INFINITY, -INFINITY, -INFINITY);
        for (int j = rp0 + lane; j < rp1; j += 32) {
            int c = g_cols[j];
            float4 q = ((const float4*)g_qagg)[c];
            m.x = fmaxf(m.x, kact.x * q.x); m.y = fmaxf(m.y, kact.y * q.y);
            m.z = fmaxf(m.z, kact.z * q.z); m.w = fmaxf(m.w, kact.w * q.w);
        }
#pragma unroll
        for (int off = 16; off > 0; off >>= 1) {
            m.x = fmaxf(m.x, __shfl_xor_sync(0xffffffffu, m.x, off));
            m.y = fmaxf(m.y, __shfl_xor_sync(0xffffffffu, m.y, off));
            m.z = fmaxf(m.z, __shfl_xor_sync(0xffffffffu, m.z, off));
            m.w = fmaxf(m.w, __shfl_xor_sync(0xffffffffu, m.w, off));
        }
        float4 sum = make_float4(0.f, 0.f, 0.f, 0.f);
        for (int j = rp0 + lane; j < rp1; j += 32) {
            int c = g_cols[j];
            float4 q = ((const float4*)g_qagg)[c];
            sum.x += __expf(kact.x * q.x - m.x);
            sum.y += __expf(kact.y * q.y - m.y);
            sum.z += __expf(kact.z * q.z - m.z);
            sum.w += __expf(kact.w * q.w - m.w);
        }
#pragma unroll
        for (int off = 16; off > 0; off >>= 1) {
            sum.x += __shfl_xor_sync(0xffffffffu, sum.x, off);
            sum.y += __shfl_xor_sync(0xffffffffu, sum.y, off);
            sum.z += __shfl_xor_sync(0xffffffffu, sum.z, off);
            sum.w += __shfl_xor_sync(0xffffffffu, sum.w, off);
        }
        float4 inv = make_float4(0.25f / (sum.x + 1e-8f), 0.25f / (sum.y + 1e-8f),
                                 0.25f / (sum.z + 1e-8f), 0.25f / (sum.w + 1e-8f));
        for (int jj = 0; jj < deg; jj++) {
            int c = __ldg(&g_cols[rp0 + jj]);
            float4 q = ((const float4*)g_qagg)[c];
            float a = __expf(kact.x * q.x - m.x) * inv.x
                    + __expf(kact.y * q.y - m.y) * inv.y
                    + __expf(kact.z * q.z - m.z) * inv.z
                    + __expf(kact.w * q.w - m.w) * inv.w;
            uint2 v = *(const uint2*)&g_hproj[(size_t)c * DIM + lane * 4];
            float2 f0 = __half22float2(*(const __half2*)&v.x);
            float2 f1 = __half22float2(*(const __half2*)&v.y);
            acc.x += a * f0.x; acc.y += a * f0.y;
            acc.z += a * f1.x; acc.w += a * f1.y;
        }
    }

    acc.x = leaky_f(acc.x); acc.y = leaky_f(acc.y);
    acc.z = leaky_f(acc.z); acc.w = leaky_f(acc.w);
    *(float4*)&out[(size_t)node * DIM + lane * 4] = acc;
}

// ---------------- launch (forked capture graph: CSR chain || projections) ----------------
extern "C" void kernel_launch(void* const* d_in, const int* in_sizes, int n_in,
                              void* d_out, int out_size) {
    const float* x  = (const float*)d_in[0];
    const int*   ei = (const int*)d_in[1];
    const float* Wq = (const float*)d_in[2];
    const float* Wk = (const float*)d_in[3];
    const float* Wl = (const float*)d_in[4];
    const float* bl = (const float*)d_in[5];
    float* out = (float*)d_out;

    const int TB = 256;
    const int E4_BLOCKS = (N_EDGES / 4 + TB - 1) / TB;          // 1563
    const int NODE_WARP_BLOCKS = (N_NODES * 32 + TB - 1) / TB;  // 6250

    // host-side resources, created once (host allocations only; no device memory)
    static cudaStream_t s1 = nullptr;
    static cudaEvent_t evFork = nullptr, evQk = nullptr, evGemm = nullptr;
    static bool streams_ok = false;
    if (!s1) {
        streams_ok =
            (cudaStreamCreateWithFlags(&s1, cudaStreamNonBlocking) == cudaSuccess) &&
            (cudaEventCreateWithFlags(&evFork, cudaEventDisableTiming) == cudaSuccess) &&
            (cudaEventCreateWithFlags(&evQk,   cudaEventDisableTiming) == cudaSuccess) &&
            (cudaEventCreateWithFlags(&evGemm, cudaEventDisableTiming) == cudaSuccess);
    }

    if (streams_ok) {
        // fork: projections on s1, CSR build on the (captured) legacy stream
        cudaEventRecord(evFork, 0);
        cudaStreamWaitEvent(s1, evFork, 0);

        k_qk<<<NODE_WARP_BLOCKS, TB, 0, s1>>>(x, Wq, Wk);
        cudaEventRecord(evQk, s1);
        k_gemm<<<(N_NODES + 127) / 128, TB, 0, s1>>>(x, Wl, bl);
        cudaEventRecord(evGemm, s1);

        k_hist<<<E4_BLOCKS, TB>>>(ei);
        k_scan<<<1, SCAN_T>>>();
        k_scatter<<<E4_BLOCKS, TB>>>(ei);

        cudaStreamWaitEvent(0, evQk, 0);     // qagg needs qk + scatter
        k_qagg_csr<<<NODE_WARP_BLOCKS, TB>>>();
        cudaStreamWaitEvent(0, evGemm, 0);   // fused needs qagg + gemm (joins s1)
        k_fused<<<NODE_WARP_BLOCKS, TB>>>(out);
    } else {
        // serial fallback
        k_hist<<<E4_BLOCKS, TB>>>(ei);
        k_scan<<<1, SCAN_T>>>();
        k_scatter<<<E4_BLOCKS, TB>>>(ei);
        k_qk<<<NODE_WARP_BLOCKS, TB>>>(x, Wq, Wk);
        k_gemm<<<(N_NODES + 127) / 128, TB>>>(x, Wl, bl);
        k_qagg_csr<<<NODE_WARP_BLOCKS, TB>>>();
        k_fused<<<NODE_WARP_BLOCKS, TB>>>(out);
    }
}